// round 9
// baseline (speedup 1.0000x reference)
#include <cuda_runtime.h>

// Device-global scratch (no allocations). Zero-init at load; last block resets
// after writing out, so graph replays stay deterministic.
__device__ unsigned long long g_mismatch_count = 0ULL;
__device__ unsigned int g_blocks_arrived = 0u;

__device__ __forceinline__ int group_of(int c) {
    return (c < 3) ? 0 : ((c < 6) ? 1 : 2);
}

__device__ __forceinline__ unsigned int mismatch(float4 a, float4 b, int t) {
    float m = a.x; int am = 0;
    if (a.y > m) { m = a.y; am = 1; }
    if (a.z > m) { m = a.z; am = 2; }
    if (a.w > m) { m = a.w; am = 3; }
    if (b.x > m) { m = b.x; am = 4; }
    if (b.y > m) { m = b.y; am = 5; }
    if (b.z > m) { m = b.z; am = 6; }
    if (b.w > m) { m = b.w; am = 7; }
    return (group_of(am) != group_of(t)) ? 1u : 0u;
}

__global__ void __launch_bounds__(256) path_loss_fused_kernel(
    const float4* __restrict__ preds,   // [batch * 2] float4 (row = 2 float4s, 32B)
    const int* __restrict__ targets,    // [batch] int32
    float* __restrict__ out,
    int batch)
{
    int gid = blockIdx.x * blockDim.x + threadIdx.x;
    int S = gridDim.x * blockDim.x;     // total threads

    unsigned int local = 0;

    if (batch == 8 * S) {
        // Exact shape: 8 stride-separated rows per thread, fully straight-line.
        // All 24 loads (16x float4 + 8x int) are independent and front-batched;
        // streaming (.cs) hints since data is touched exactly once.
        float4 a[8], b[8];
        int t[8];
        #pragma unroll
        for (int k = 0; k < 8; k++) {
            int i = gid + k * S;
            a[k] = __ldcs(preds + 2 * i);
            b[k] = __ldcs(preds + 2 * i + 1);
            t[k] = __ldcs(targets + i);
        }
        #pragma unroll
        for (int k = 0; k < 8; k++)
            local += mismatch(a[k], b[k], t[k]);
    } else {
        // Generic fallback: 4-row stride unroll + tail.
        int i = gid;
        for (; i + 3 * S < batch; i += 4 * S) {
            int i0 = i, i1 = i + S, i2 = i + 2 * S, i3 = i + 3 * S;
            float4 a0 = __ldcs(preds + 2 * i0), a1 = __ldcs(preds + 2 * i1);
            float4 a2 = __ldcs(preds + 2 * i2), a3 = __ldcs(preds + 2 * i3);
            float4 b0 = __ldcs(preds + 2 * i0 + 1), b1 = __ldcs(preds + 2 * i1 + 1);
            float4 b2 = __ldcs(preds + 2 * i2 + 1), b3 = __ldcs(preds + 2 * i3 + 1);
            int t0 = __ldcs(targets + i0), t1 = __ldcs(targets + i1);
            int t2 = __ldcs(targets + i2), t3 = __ldcs(targets + i3);
            local += mismatch(a0, b0, t0);
            local += mismatch(a1, b1, t1);
            local += mismatch(a2, b2, t2);
            local += mismatch(a3, b3, t3);
        }
        for (; i < batch; i += S) {
            float4 a = __ldcs(preds + 2 * i), b = __ldcs(preds + 2 * i + 1);
            local += mismatch(a, b, __ldcs(targets + i));
        }
    }

    // warp reduction
    #pragma unroll
    for (int off = 16; off > 0; off >>= 1)
        local += __shfl_down_sync(0xFFFFFFFFu, local, off);

    __shared__ unsigned int warp_sums[8];
    int lane = threadIdx.x & 31;
    int wid = threadIdx.x >> 5;
    if (lane == 0) warp_sums[wid] = local;
    __syncthreads();

    if (wid == 0) {
        unsigned int v = (lane < (blockDim.x >> 5)) ? warp_sums[lane] : 0u;
        #pragma unroll
        for (int off = 4; off > 0; off >>= 1)
            v += __shfl_down_sync(0xFFFFFFFFu, v, off);

        if (lane == 0) {
            atomicAdd(&g_mismatch_count, (unsigned long long)v);
            __threadfence();
            unsigned int ticket = atomicAdd(&g_blocks_arrived, 1u);
            if (ticket == gridDim.x - 1) {
                unsigned long long total = atomicAdd(&g_mismatch_count, 0ULL);
                *out = (float)((double)total / (double)batch);
                g_mismatch_count = 0ULL;
                g_blocks_arrived = 0u;
            }
        }
    }
}

extern "C" void kernel_launch(void* const* d_in, const int* in_sizes, int n_in,
                              void* d_out, int out_size) {
    const float4* preds = (const float4*)d_in[0];   // [B, 8] f32
    const int* targets = (const int*)d_in[1];       // [B] int32
    int batch = in_sizes[0] / 8;
    float* out = (float*)d_out;

    const int threads = 256;
    int blocks = 2048;   // 524288 threads -> exactly 8 rows/thread at B = 4.19M
    path_loss_fused_kernel<<<blocks, threads>>>(preds, targets, out, batch);
}

// round 10
// speedup vs baseline: 1.0234x; 1.0234x over previous
#include <cuda_runtime.h>

// Device-global scratch (no allocations). Zero-init at load; last block resets
// after writing out, so graph replays stay deterministic.
__device__ unsigned long long g_mismatch_count = 0ULL;
__device__ unsigned int g_blocks_arrived = 0u;

__device__ __forceinline__ int group_of(int c) {
    return (c < 3) ? 0 : ((c < 6) ? 1 : 2);
}

__device__ __forceinline__ unsigned int mismatch(float4 a, float4 b, int t) {
    float m = a.x; int am = 0;
    if (a.y > m) { m = a.y; am = 1; }
    if (a.z > m) { m = a.z; am = 2; }
    if (a.w > m) { m = a.w; am = 3; }
    if (b.x > m) { m = b.x; am = 4; }
    if (b.y > m) { m = b.y; am = 5; }
    if (b.z > m) { m = b.z; am = 6; }
    if (b.w > m) { m = b.w; am = 7; }
    return (group_of(am) != group_of(t)) ? 1u : 0u;
}

// asm-volatile loads: ptxas cannot reorder these relative to each other,
// guaranteeing a genuine front-batched load group (real MLP).
__device__ __forceinline__ void ld_row(const float4* __restrict__ p,
                                       float4& a, float4& b) {
    asm volatile("ld.global.nc.v4.f32 {%0,%1,%2,%3}, [%4];"
                 : "=f"(a.x), "=f"(a.y), "=f"(a.z), "=f"(a.w)
                 : "l"(p));
    asm volatile("ld.global.nc.v4.f32 {%0,%1,%2,%3}, [%4];"
                 : "=f"(b.x), "=f"(b.y), "=f"(b.z), "=f"(b.w)
                 : "l"(p + 1));
}

__device__ __forceinline__ int ld_tgt(const int* __restrict__ p) {
    int v;
    asm volatile("ld.global.nc.b32 %0, [%1];" : "=r"(v) : "l"(p));
    return v;
}

__global__ void __launch_bounds__(256) path_loss_fused_kernel(
    const float4* __restrict__ preds,   // [batch * 2] float4 (row = 32B)
    const int* __restrict__ targets,    // [batch] int32
    float* __restrict__ out,
    int batch)
{
    int gid = blockIdx.x * blockDim.x + threadIdx.x;
    int S = gridDim.x * blockDim.x;

    unsigned int local = 0;

    // Stride-separated 4-row groups; each group's 12 loads are asm-volatile
    // front-batched (8x LDG.128 + 4x LDG.32 in flight before any compute).
    int i = gid;
    for (; i + 3 * S < batch; i += 4 * S) {
        int i0 = i, i1 = i + S, i2 = i + 2 * S, i3 = i + 3 * S;
        float4 a0, b0, a1, b1, a2, b2, a3, b3;
        ld_row(preds + 2 * i0, a0, b0);
        ld_row(preds + 2 * i1, a1, b1);
        ld_row(preds + 2 * i2, a2, b2);
        ld_row(preds + 2 * i3, a3, b3);
        int t0 = ld_tgt(targets + i0);
        int t1 = ld_tgt(targets + i1);
        int t2 = ld_tgt(targets + i2);
        int t3 = ld_tgt(targets + i3);

        local += mismatch(a0, b0, t0);
        local += mismatch(a1, b1, t1);
        local += mismatch(a2, b2, t2);
        local += mismatch(a3, b3, t3);
    }
    for (; i < batch; i += S) {
        float4 a, b;
        ld_row(preds + 2 * i, a, b);
        local += mismatch(a, b, ld_tgt(targets + i));
    }

    // warp reduction
    #pragma unroll
    for (int off = 16; off > 0; off >>= 1)
        local += __shfl_down_sync(0xFFFFFFFFu, local, off);

    __shared__ unsigned int warp_sums[8];
    int lane = threadIdx.x & 31;
    int wid = threadIdx.x >> 5;
    if (lane == 0) warp_sums[wid] = local;
    __syncthreads();

    if (wid == 0) {
        unsigned int v = (lane < (blockDim.x >> 5)) ? warp_sums[lane] : 0u;
        #pragma unroll
        for (int off = 4; off > 0; off >>= 1)
            v += __shfl_down_sync(0xFFFFFFFFu, v, off);

        if (lane == 0) {
            atomicAdd(&g_mismatch_count, (unsigned long long)v);
            __threadfence();
            unsigned int ticket = atomicAdd(&g_blocks_arrived, 1u);
            if (ticket == gridDim.x - 1) {
                unsigned long long total = atomicAdd(&g_mismatch_count, 0ULL);
                *out = (float)((double)total / (double)batch);
                g_mismatch_count = 0ULL;
                g_blocks_arrived = 0u;
            }
        }
    }
}

extern "C" void kernel_launch(void* const* d_in, const int* in_sizes, int n_in,
                              void* d_out, int out_size) {
    const float4* preds = (const float4*)d_in[0];   // [B, 8] f32
    const int* targets = (const int*)d_in[1];       // [B] int32
    int batch = in_sizes[0] / 8;
    float* out = (float*)d_out;

    const int threads = 256;
    int blocks = 2048;   // 524288 threads -> 8 rows/thread (2 unrolled groups)
    path_loss_fused_kernel<<<blocks, threads>>>(preds, targets, out, batch);
}

// round 11
// speedup vs baseline: 1.0837x; 1.0590x over previous
#include <cuda_runtime.h>

// Device-global scratch (no allocations). Zero-init at load; last block resets
// after writing out, so graph replays stay deterministic.
__device__ unsigned long long g_mismatch_count = 0ULL;
__device__ unsigned int g_blocks_arrived = 0u;

__device__ __forceinline__ int group_of(int c) {
    return (c < 3) ? 0 : ((c < 6) ? 1 : 2);
}

__device__ __forceinline__ unsigned int mismatch(float4 a, float4 b, int t) {
    float m = a.x; int am = 0;
    if (a.y > m) { m = a.y; am = 1; }
    if (a.z > m) { m = a.z; am = 2; }
    if (a.w > m) { m = a.w; am = 3; }
    if (b.x > m) { m = b.x; am = 4; }
    if (b.y > m) { m = b.y; am = 5; }
    if (b.z > m) { m = b.z; am = 6; }
    if (b.w > m) { m = b.w; am = 7; }
    return (group_of(am) != group_of(t)) ? 1u : 0u;
}

// asm-volatile loads: pinned issue order among themselves.
__device__ __forceinline__ void ld_row(const float4* __restrict__ p,
                                       float4& a, float4& b) {
    asm volatile("ld.global.nc.v4.f32 {%0,%1,%2,%3}, [%4];"
                 : "=f"(a.x), "=f"(a.y), "=f"(a.z), "=f"(a.w)
                 : "l"(p));
    asm volatile("ld.global.nc.v4.f32 {%0,%1,%2,%3}, [%4];"
                 : "=f"(b.x), "=f"(b.y), "=f"(b.z), "=f"(b.w)
                 : "l"(p + 1));
}

__device__ __forceinline__ int ld_tgt(const int* __restrict__ p) {
    int v;
    asm volatile("ld.global.nc.b32 %0, [%1];" : "=r"(v) : "l"(p));
    return v;
}

// __launch_bounds__(256, 4): 4 blocks/SM target -> ~64-reg budget, so the
// 8-row front batch (16 float4 + 8 int live) can actually be allocated.
__global__ void __launch_bounds__(256, 4) path_loss_fused_kernel(
    const float4* __restrict__ preds,   // [batch * 2] float4 (row = 32B)
    const int* __restrict__ targets,    // [batch] int32
    float* __restrict__ out,
    int batch)
{
    int gid = blockIdx.x * blockDim.x + threadIdx.x;
    int S = gridDim.x * blockDim.x;

    unsigned int local = 0;

    // 8 stride-separated rows per iteration, all 24 loads front-batched.
    int i = gid;
    for (; i + 7 * S < batch; i += 8 * S) {
        float4 a[8], b[8];
        int t[8];
        #pragma unroll
        for (int k = 0; k < 8; k++)
            ld_row(preds + 2 * (i + k * S), a[k], b[k]);
        #pragma unroll
        for (int k = 0; k < 8; k++)
            t[k] = ld_tgt(targets + i + k * S);
        #pragma unroll
        for (int k = 0; k < 8; k++)
            local += mismatch(a[k], b[k], t[k]);
    }
    // Tail: per-row grid-stride.
    for (; i < batch; i += S) {
        float4 a, b;
        ld_row(preds + 2 * i, a, b);
        local += mismatch(a, b, ld_tgt(targets + i));
    }

    // warp reduction
    #pragma unroll
    for (int off = 16; off > 0; off >>= 1)
        local += __shfl_down_sync(0xFFFFFFFFu, local, off);

    __shared__ unsigned int warp_sums[8];
    int lane = threadIdx.x & 31;
    int wid = threadIdx.x >> 5;
    if (lane == 0) warp_sums[wid] = local;
    __syncthreads();

    if (wid == 0) {
        unsigned int v = (lane < (blockDim.x >> 5)) ? warp_sums[lane] : 0u;
        #pragma unroll
        for (int off = 4; off > 0; off >>= 1)
            v += __shfl_down_sync(0xFFFFFFFFu, v, off);

        if (lane == 0) {
            atomicAdd(&g_mismatch_count, (unsigned long long)v);
            __threadfence();
            unsigned int ticket = atomicAdd(&g_blocks_arrived, 1u);
            if (ticket == gridDim.x - 1) {
                unsigned long long total = atomicAdd(&g_mismatch_count, 0ULL);
                *out = (float)((double)total / (double)batch);
                g_mismatch_count = 0ULL;
                g_blocks_arrived = 0u;
            }
        }
    }
}

extern "C" void kernel_launch(void* const* d_in, const int* in_sizes, int n_in,
                              void* d_out, int out_size) {
    const float4* preds = (const float4*)d_in[0];   // [B, 8] f32
    const int* targets = (const int*)d_in[1];       // [B] int32
    int batch = in_sizes[0] / 8;
    float* out = (float*)d_out;

    const int threads = 256;
    // Persistent single wave: 148 SMs x 4 blocks/SM resident.
    int blocks = 148 * 4;
    path_loss_fused_kernel<<<blocks, threads>>>(preds, targets, out, batch);
}